// round 2
// baseline (speedup 1.0000x reference)
#include <cuda_runtime.h>
#include <cuda_bf16.h>

#define BDIM 512
#define S_LEN 4096
#define B_ROWS 4096

__device__ float g_rowvals[B_ROWS];
__device__ unsigned int g_count = 0;

__global__ __launch_bounds__(BDIM) void mtcut_fused_kernel(
    const float* __restrict__ cut_y,
    const int*   __restrict__ cut_label,
    const float* __restrict__ rerank_y,
    float* __restrict__ out)
{
    const int b    = blockIdx.x;
    const int t    = threadIdx.x;
    const int lane = t & 31;
    const int wid  = t >> 5;

    const float4* y4 = reinterpret_cast<const float4*>(cut_y + (size_t)b * S_LEN);
    const int4*   l4 = reinterpret_cast<const int4*>(cut_label + (size_t)b * S_LEN);

    float4 ya = y4[2 * t];
    float4 yb = y4[2 * t + 1];
    int4   la = l4[2 * t];
    int4   lb = l4[2 * t + 1];

    int   lab[8] = {la.x, la.y, la.z, la.w, lb.x, lb.y, lb.z, lb.w};
    float yv[8]  = {ya.x, ya.y, ya.z, ya.w, yb.x, yb.y, yb.z, yb.w};

    int tsum = 0;
    #pragma unroll
    for (int j = 0; j < 8; j++) tsum += lab[j];

    // warp inclusive scan of per-thread label sums
    int incl = tsum;
    #pragma unroll
    for (int d = 1; d < 32; d <<= 1) {
        int v = __shfl_up_sync(0xffffffffu, incl, d);
        if (lane >= d) incl += v;
    }

    __shared__ int wsum[16];
    __shared__ int woff[17];
    if (lane == 31) wsum[wid] = incl;
    __syncthreads();
    if (t == 0) {
        int acc = 0;
        #pragma unroll
        for (int w = 0; w < 16; w++) { woff[w] = acc; acc += wsum[w]; }
        woff[16] = acc;
    }
    __syncthreads();

    const float T = (float)woff[16];       // row total of labels
    int c = woff[wid] + incl - tsum;       // exclusive prefix for this thread

    // r = 2c/(k+T)  == f1 weight (incl. all where-guards: c==0 -> r==0)
    const float C = 2.0f / 0.95f;          // 2/TAU
    float esum = 0.f, lsum = 0.f;
    const float kbase = (float)(t * 8);
    #pragma unroll
    for (int j = 0; j < 8; j++) {
        c += lab[j];
        float k   = kbase + (float)(j + 1);
        float arg = C * __fdividef((float)c, k + T);
        esum += __expf(arg);
        lsum += __logf(yv[j]);
    }

    // block reduce esum, lsum
    #pragma unroll
    for (int d = 16; d; d >>= 1) {
        esum += __shfl_down_sync(0xffffffffu, esum, d);
        lsum += __shfl_down_sync(0xffffffffu, lsum, d);
    }
    __shared__ float se[16], sl[16];
    if (lane == 0) { se[wid] = esum; sl[wid] = lsum; }
    __syncthreads();

    __shared__ unsigned int s_rank;
    if (wid == 0) {
        float e = (lane < 16) ? se[lane] : 0.f;
        float l = (lane < 16) ? sl[lane] : 0.f;
        #pragma unroll
        for (int d = 8; d; d >>= 1) {
            e += __shfl_down_sync(0xffffffffu, e, d);
            l += __shfl_down_sync(0xffffffffu, l, d);
        }
        if (lane == 0) {
            // this block's rerank pair: hinge = max(0, neg - pos + MARGIN)
            float2 pn = reinterpret_cast<const float2*>(rerank_y)[b];
            float hinge = fmaxf(0.f, pn.y - pn.x + 1.0f);
            // combined, pre-scaled contribution of this row
            g_rowvals[b] = (hinge - l / e) * (1.0f / (float)B_ROWS);
            __threadfence();
            s_rank = atomicAdd(&g_count, 1u);
        }
    }
    __syncthreads();

    if (s_rank == B_ROWS - 1) {
        // last block: reduce the 4096 row contributions and write the scalar
        float a = 0.f;
        #pragma unroll
        for (int i = t; i < B_ROWS; i += BDIM) a += g_rowvals[i];
        #pragma unroll
        for (int d = 16; d; d >>= 1)
            a += __shfl_down_sync(0xffffffffu, a, d);
        __shared__ float sa[16];
        if (lane == 0) sa[wid] = a;
        __syncthreads();
        if (wid == 0) {
            float av = (lane < 16) ? sa[lane] : 0.f;
            #pragma unroll
            for (int d = 8; d; d >>= 1)
                av += __shfl_down_sync(0xffffffffu, av, d);
            if (lane == 0) {
                out[0] = av;
                g_count = 0;   // reset for next graph replay (deterministic)
            }
        }
    }
}

extern "C" void kernel_launch(void* const* d_in, const int* in_sizes, int n_in,
                              void* d_out, int out_size)
{
    const float* rerank_y  = (const float*)d_in[0];   // (8192,1)
    const float* cut_y     = (const float*)d_in[1];   // (4096,4096,1)
    const int*   cut_label = (const int*)d_in[3];     // (4096,4096)
    float* out = (float*)d_out;

    mtcut_fused_kernel<<<B_ROWS, BDIM>>>(cut_y, cut_label, rerank_y, out);
}

// round 3
// speedup vs baseline: 1.1317x; 1.1317x over previous
#include <cuda_runtime.h>
#include <cuda_bf16.h>

#define BDIM 512
#define S_LEN 4096
#define B_ROWS 4096

__device__ float g_rowvals[B_ROWS];

__device__ __forceinline__ float ex2_approx(float x) {
    float r; asm("ex2.approx.f32 %0, %1;" : "=f"(r) : "f"(x)); return r;
}
__device__ __forceinline__ float lg2_approx(float x) {
    float r; asm("lg2.approx.f32 %0, %1;" : "=f"(r) : "f"(x)); return r;
}

__global__ __launch_bounds__(BDIM) void mtcut_row_kernel(
    const float* __restrict__ cut_y,
    const int*   __restrict__ cut_label,
    const float* __restrict__ rerank_y)
{
    const int b    = blockIdx.x;
    const int t    = threadIdx.x;
    const int lane = t & 31;
    const int wid  = t >> 5;

    const float4* y4 = reinterpret_cast<const float4*>(cut_y + (size_t)b * S_LEN);
    const int4*   l4 = reinterpret_cast<const int4*>(cut_label + (size_t)b * S_LEN);

    float4 ya = __ldcs(&y4[2 * t]);
    float4 yb = __ldcs(&y4[2 * t + 1]);
    int4   la = __ldcs(&l4[2 * t]);
    int4   lb = __ldcs(&l4[2 * t + 1]);

    int   lab[8] = {la.x, la.y, la.z, la.w, lb.x, lb.y, lb.z, lb.w};
    float yv[8]  = {ya.x, ya.y, ya.z, ya.w, yb.x, yb.y, yb.z, yb.w};

    // --- independent work first: sum of lg2(y) (fills load/barrier latency) ---
    float lg2sum = 0.f;
    #pragma unroll
    for (int j = 0; j < 8; j++) lg2sum += lg2_approx(yv[j]);

    // --- label prefix sum ---
    int tsum = 0;
    #pragma unroll
    for (int j = 0; j < 8; j++) tsum += lab[j];

    int incl = tsum;
    #pragma unroll
    for (int d = 1; d < 32; d <<= 1) {
        int v = __shfl_up_sync(0xffffffffu, incl, d);
        if (lane >= d) incl += v;
    }

    __shared__ int wsum[16];
    __shared__ int woff[17];
    if (lane == 31) wsum[wid] = incl;
    __syncthreads();
    if (t == 0) {
        int acc = 0;
        #pragma unroll
        for (int w = 0; w < 16; w++) { woff[w] = acc; acc += wsum[w]; }
        woff[16] = acc;
    }
    __syncthreads();

    const float T = (float)woff[16];       // row total of labels
    int c = woff[wid] + incl - tsum;       // exclusive prefix for this thread

    // r/tau = 2c/((k+T)*tau); exp(x) = ex2(x*log2e) -> fold into one constant
    const float Cx = 2.0f / (0.95f * 0.69314718055994531f);   // 2/(tau*ln2)
    float esum = 0.f;
    const float kbase = (float)(t * 8) + T;
    #pragma unroll
    for (int j = 0; j < 8; j++) {
        c += lab[j];
        float arg = __fdividef((float)c * Cx, kbase + (float)(j + 1));
        esum += ex2_approx(arg);
    }

    // block reduce esum, lg2sum
    #pragma unroll
    for (int d = 16; d; d >>= 1) {
        esum   += __shfl_down_sync(0xffffffffu, esum, d);
        lg2sum += __shfl_down_sync(0xffffffffu, lg2sum, d);
    }
    __shared__ float se[16], sl[16];
    if (lane == 0) { se[wid] = esum; sl[wid] = lg2sum; }
    __syncthreads();
    if (wid == 0) {
        float e = (lane < 16) ? se[lane] : 0.f;
        float l = (lane < 16) ? sl[lane] : 0.f;
        #pragma unroll
        for (int d = 8; d; d >>= 1) {
            e += __shfl_down_sync(0xffffffffu, e, d);
            l += __shfl_down_sync(0xffffffffu, l, d);
        }
        if (lane == 0) {
            float lsum = l * 0.69314718055994531f;   // back to natural log
            float2 pn = reinterpret_cast<const float2*>(rerank_y)[b];
            float hinge = fmaxf(0.f, pn.y - pn.x + 1.0f);
            g_rowvals[b] = (hinge - lsum / e) * (1.0f / (float)B_ROWS);
        }
    }
}

__global__ __launch_bounds__(1024) void mtcut_finalize_kernel(float* __restrict__ out)
{
    const int t    = threadIdx.x;
    const int lane = t & 31;
    const int wid  = t >> 5;

    float a = 0.f;
    #pragma unroll
    for (int i = t; i < B_ROWS; i += 1024) a += g_rowvals[i];

    #pragma unroll
    for (int d = 16; d; d >>= 1)
        a += __shfl_down_sync(0xffffffffu, a, d);
    __shared__ float sa[32];
    if (lane == 0) sa[wid] = a;
    __syncthreads();
    if (wid == 0) {
        float av = (lane < 32) ? sa[lane] : 0.f;
        #pragma unroll
        for (int d = 16; d; d >>= 1)
            av += __shfl_down_sync(0xffffffffu, av, d);
        if (lane == 0) out[0] = av;
    }
}

extern "C" void kernel_launch(void* const* d_in, const int* in_sizes, int n_in,
                              void* d_out, int out_size)
{
    const float* rerank_y  = (const float*)d_in[0];   // (8192,1)
    const float* cut_y     = (const float*)d_in[1];   // (4096,4096,1)
    const int*   cut_label = (const int*)d_in[3];     // (4096,4096)
    float* out = (float*)d_out;

    mtcut_row_kernel<<<B_ROWS, BDIM>>>(cut_y, cut_label, rerank_y);
    mtcut_finalize_kernel<<<1, 1024>>>(out);
}